// round 2
// baseline (speedup 1.0000x reference)
#include <cuda_runtime.h>
#include <cstdint>
#include <cstddef>

// Problem constants
#define BATCH   2
#define NPTS    8192
#define DIM     128
#define KOUT    17            // ranks 1..17 (skip self)
#define QT      128           // queries per CTA
#define CT      128           // candidates per tile
#define NTILES  (NPTS / CT)   // 64
#define LD      132           // C-tile row pitch (floats)
#define QLD     256           // duplicated Q-tile row pitch (floats)

// smem layout (floats)
#define OFF_QD   0                              // Qdup: 128 x 256
#define OFF_CS   (DIM * QLD)                    // 32768  (C tile / D2 tile alias)
#define OFF_SQQ  (DIM * QLD + DIM * LD)         // 49664
#define OFF_SQC  (OFF_SQQ + QT)
#define SMEM_FLOATS (OFF_SQC + CT)              // 49920
#define SMEM_BYTES  (SMEM_FLOATS * 4)           // 199680

// Scratch (device globals: allocation-free rule)
__device__ float g_xT[BATCH * DIM * NPTS];   // x transposed: [b][k][n]
__device__ float g_sq[BATCH * NPTS];         // squared norms

// Packed dual-fp32 FMA: lane-wise fma.rn, bit-identical to two scalar fmaf.
__device__ __forceinline__ unsigned long long fma2(unsigned long long a,
                                                   unsigned long long b,
                                                   unsigned long long c) {
    unsigned long long d;
    asm("fma.rn.f32x2 %0, %1, %2, %3;" : "=l"(d) : "l"(a), "l"(b), "l"(c));
    return d;
}

// ---------------------------------------------------------------------------
// Prep kernel 1: tiled transpose x[b][n][k] -> g_xT[b][k][n]
// ---------------------------------------------------------------------------
__global__ void knn_transpose_kernel(const float* __restrict__ x) {
    __shared__ float t[32][33];
    const int b  = blockIdx.z;
    const int n0 = blockIdx.y * 32;
    const int k0 = blockIdx.x * 32;
    const int tx = threadIdx.x;
    const int ty = threadIdx.y;
#pragma unroll
    for (int i = 0; i < 32; i += 8)
        t[ty + i][tx] = x[((size_t)(b * NPTS + n0 + ty + i)) * DIM + k0 + tx];
    __syncthreads();
#pragma unroll
    for (int i = 0; i < 32; i += 8)
        g_xT[(size_t)b * DIM * NPTS + (size_t)(k0 + ty + i) * NPTS + n0 + tx] = t[tx][ty + i];
}

// ---------------------------------------------------------------------------
// Prep kernel 2: squared norms (one warp per point)
// ---------------------------------------------------------------------------
__global__ void knn_sq_kernel(const float* __restrict__ x) {
    const int n    = blockIdx.x * 8 + (threadIdx.x >> 5);
    const int lane = threadIdx.x & 31;
    float4 v = *(const float4*)(x + (size_t)n * DIM + lane * 4);
    float s = v.x * v.x + v.y * v.y + v.z * v.z + v.w * v.w;
#pragma unroll
    for (int o = 16; o > 0; o >>= 1) s += __shfl_xor_sync(0xFFFFFFFFu, s, o);
    if (lane == 0) g_sq[n] = s;
}

// ---------------------------------------------------------------------------
// Main fused GEMM + top-K kernel
// ---------------------------------------------------------------------------
#define TRY_INSERT(dv, iv)                                                      \
    do {                                                                        \
        float _d = (dv);                                                        \
        if (_d <= th) {                                                         \
            int _i = (iv);                                                      \
            if (_d < bd[16] || (_d == bd[16] && _i < bi[16])) {                 \
                bd[16] = _d; bi[16] = _i;                                       \
                _Pragma("unroll")                                               \
                for (int _s = 16; _s > 0; --_s) {                               \
                    bool _sw = (bd[_s] < bd[_s - 1]) ||                         \
                               (bd[_s] == bd[_s - 1] && bi[_s] < bi[_s - 1]);   \
                    if (_sw) {                                                  \
                        float _td = bd[_s]; bd[_s] = bd[_s - 1]; bd[_s - 1] = _td; \
                        int _ti = bi[_s]; bi[_s] = bi[_s - 1]; bi[_s - 1] = _ti;  \
                    }                                                           \
                }                                                               \
                th = bd[16];                                                    \
            }                                                                   \
        }                                                                       \
    } while (0)

__global__ void __launch_bounds__(256, 1)
knn_main_kernel(float* __restrict__ outDist, float* __restrict__ outIdx) {
    extern __shared__ float sm[];
    float* Qd  = sm + OFF_QD;       // duplicated Q tile [128][256]
    float* Cs  = sm + OFF_CS;       // C tile [128][132]; aliased as D2 tile
    float* Ds  = Cs;                // alias: C dead after GEMM each tile
    float* sqQ = sm + OFF_SQQ;
    float* sqC = sm + OFF_SQC;

    const int tid = threadIdx.x;
    const int b   = blockIdx.y;
    const int q0  = blockIdx.x * QT;
    const float* xT  = g_xT + (size_t)b * DIM * NPTS;
    const float* sqg = g_sq + (size_t)b * NPTS;

    const float FINF = __int_as_float(0x7f800000);

    // ---- load Q tile, duplicating each value: Qd[k][2c]=Qd[k][2c+1]=Q[k][c] ----
#pragma unroll
    for (int i = 0; i < 16; ++i) {
        int f = tid + i * 256;
        int k = f >> 5, c4 = f & 31;
        float4 v = *(const float4*)(xT + (size_t)k * NPTS + q0 + c4 * 4);
        float* dst = Qd + k * QLD + c4 * 8;
        *(float4*)(dst)     = make_float4(v.x, v.x, v.y, v.y);
        *(float4*)(dst + 4) = make_float4(v.z, v.z, v.w, v.w);
    }
    if (tid < QT) sqQ[tid] = sqg[q0 + tid];

    // ---- top-K state (registers) ----
    float bd[KOUT]; int bi[KOUT];
#pragma unroll
    for (int s = 0; s < KOUT; ++s) { bd[s] = FINF; bi[s] = 0x7FFFFFFF; }
    float th = FINF;

    const int ty = tid >> 4, tx = tid & 15;           // GEMM 16x16 thread grid
    const int selR = tid >> 1, selC = (tid & 1) * 64; // selection: 2 threads/row

    for (int ct = 0; ct < NTILES; ++ct) {
        const int c0 = ct * CT;
        __syncthreads();   // prev selection (reads Ds=Cs) done before reload
        // ---- load C tile ----
#pragma unroll
        for (int i = 0; i < 16; ++i) {
            int f = tid + i * 256;
            int k = f >> 5, c4 = f & 31;
            *(float4*)(Cs + k * LD + c4 * 4) =
                *(const float4*)(xT + (size_t)k * NPTS + c0 + c4 * 4);
        }
        if (tid < CT) sqC[tid] = sqg[c0 + tid];
        __syncthreads();

        // ---- 128x128x128 fp32 GEMM via packed f32x2, 8x8 per thread ----
        unsigned long long acc2[8][4];
#pragma unroll
        for (int i = 0; i < 8; ++i)
#pragma unroll
            for (int j = 0; j < 4; ++j) acc2[i][j] = 0ULL;

#pragma unroll 8
        for (int kk = 0; kk < DIM; ++kk) {
            const float* qr = Qd + kk * QLD + (ty << 4);   // 8 dup pairs
            const float* cr = Cs + kk * LD + (tx << 3);    // 4 adjacent pairs
            ulonglong2 a0 = *(const ulonglong2*)(qr);
            ulonglong2 a1 = *(const ulonglong2*)(qr + 4);
            ulonglong2 a2 = *(const ulonglong2*)(qr + 8);
            ulonglong2 a3 = *(const ulonglong2*)(qr + 12);
            ulonglong2 b0 = *(const ulonglong2*)(cr);
            ulonglong2 b1 = *(const ulonglong2*)(cr + 4);
            unsigned long long A[8] = {a0.x, a0.y, a1.x, a1.y, a2.x, a2.y, a3.x, a3.y};
            unsigned long long B[4] = {b0.x, b0.y, b1.x, b1.y};
#pragma unroll
            for (int i = 0; i < 8; ++i)
#pragma unroll
                for (int j = 0; j < 4; ++j)
                    acc2[i][j] = fma2(A[i], B[j], acc2[i][j]);
        }
        __syncthreads();   // all GEMM reads of Cs complete before Ds writes

        // ---- epilogue: d2 = max(sqi + sqj - 2*dot, 0); self -> +inf ----
        float si[8], sj[8];
#pragma unroll
        for (int i = 0; i < 8; ++i) si[i] = sqQ[(ty << 3) + i];
#pragma unroll
        for (int j = 0; j < 8; ++j) sj[j] = sqC ? 0.f : 0.f;  // placeholder
        // (sqC read below — Cs alias only covers tile data, sqC separate)
#pragma unroll
        for (int j = 0; j < 8; ++j) sj[j] = sqC[(tx << 3) + j];
        const bool diagBlk = (c0 == q0);
#pragma unroll
        for (int i = 0; i < 8; ++i) {
            const int qg = q0 + (ty << 3) + i;
            float* drow = Ds + ((ty << 3) + i) * LD + (tx << 3);
#pragma unroll
            for (int g = 0; g < 8; g += 4) {
                float2 p0 = *(float2*)&acc2[i][(g >> 1) + 0];
                float2 p1 = *(float2*)&acc2[i][(g >> 1) + 1];
                float d0 = fmaxf(fmaf(-2.f, p0.x, si[i] + sj[g + 0]), 0.f);
                float d1 = fmaxf(fmaf(-2.f, p0.y, si[i] + sj[g + 1]), 0.f);
                float d2 = fmaxf(fmaf(-2.f, p1.x, si[i] + sj[g + 2]), 0.f);
                float d3 = fmaxf(fmaf(-2.f, p1.y, si[i] + sj[g + 3]), 0.f);
                if (diagBlk) {
                    const int cg = c0 + (tx << 3) + g;
                    if (qg == cg + 0) d0 = FINF;
                    if (qg == cg + 1) d1 = FINF;
                    if (qg == cg + 2) d2 = FINF;
                    if (qg == cg + 3) d3 = FINF;
                }
                *(float4*)(drow + g) = make_float4(d0, d1, d2, d3);
            }
        }
        __syncthreads();

        // ---- selection: each thread scans 64 d2 values of one query row ----
        const float* drow = Ds + selR * LD + selC;
#pragma unroll 1
        for (int j4 = 0; j4 < 16; ++j4) {
            float4 v = *(const float4*)(drow + j4 * 4);
            const int cb = c0 + selC + j4 * 4;
            TRY_INSERT(v.x, cb + 0);
            TRY_INSERT(v.y, cb + 1);
            TRY_INSERT(v.z, cb + 2);
            TRY_INSERT(v.w, cb + 3);
        }
    }

    // ---- merge half-lists, sqrt, stable resort by (d, idx), store ----
    __syncthreads();                       // selections done; reuse Ds region
    float* md = Ds;                        // 256*17 floats
    int*   mi = (int*)(Ds + 256 * KOUT);   // 256*17 ints
#pragma unroll
    for (int s = 0; s < KOUT; ++s) { md[tid * KOUT + s] = bd[s]; mi[tid * KOUT + s] = bi[s]; }
    __syncthreads();

    if (tid < QT) {
        const float* da = md + (tid * 2) * KOUT;
        const int*   ia = mi + (tid * 2) * KOUT;
        const float* db = md + (tid * 2 + 1) * KOUT;
        const int*   ib = mi + (tid * 2 + 1) * KOUT;
        float od[KOUT]; int oi[KOUT];
        int pa = 0, pb = 0;
        for (int s = 0; s < KOUT; ++s) {
            float d1 = da[pa]; int i1 = ia[pa];
            float d2 = db[pb]; int i2 = ib[pb];
            bool takeA = (d1 < d2) || (d1 == d2 && i1 < i2);
            if (takeA) { od[s] = d1; oi[s] = i1; ++pa; }
            else       { od[s] = d2; oi[s] = i2; ++pb; }
        }
        for (int s = 0; s < KOUT; ++s) od[s] = sqrtf(od[s]);
        for (int s = 1; s < KOUT; ++s) {
            float dv = od[s]; int iv = oi[s]; int t = s - 1;
            while (t >= 0 && (od[t] > dv || (od[t] == dv && oi[t] > iv))) {
                od[t + 1] = od[t]; oi[t + 1] = oi[t]; --t;
            }
            od[t + 1] = dv; oi[t + 1] = iv;
        }
        const size_t base = (size_t)(b * NPTS + q0 + tid) * KOUT;
        for (int s = 0; s < KOUT; ++s) {
            outDist[base + s] = od[s];
            if (outIdx) outIdx[base + s] = (float)oi[s];
        }
    }
}

// ---------------------------------------------------------------------------
// Launch
// ---------------------------------------------------------------------------
extern "C" void kernel_launch(void* const* d_in, const int* in_sizes, int n_in,
                              void* d_out, int out_size) {
    const float* x = (const float*)d_in[0];
    float* out = (float*)d_out;

    const int ND = BATCH * NPTS * KOUT;       // 278528
    const int XE = BATCH * NPTS * DIM;        // 2097152

    float* outDist = out;
    float* outIdx  = (out_size >= 2 * ND) ? (out + ND) : nullptr;

    cudaFuncSetAttribute(knn_main_kernel,
                         cudaFuncAttributeMaxDynamicSharedMemorySize, SMEM_BYTES);

    knn_transpose_kernel<<<dim3(DIM / 32, NPTS / 32, BATCH), dim3(32, 8)>>>(x);
    knn_sq_kernel<<<(BATCH * NPTS) / 8, 256>>>(x);
    knn_main_kernel<<<dim3(NPTS / QT, BATCH), 256, SMEM_BYTES>>>(outDist, outIdx);

    if (out_size >= 2 * ND + 2 * XE) {
        cudaMemcpyAsync(out + 2 * ND, x, (size_t)XE * sizeof(float),
                        cudaMemcpyDeviceToDevice);
        cudaMemcpyAsync(out + 2 * ND + XE, x, (size_t)XE * sizeof(float),
                        cudaMemcpyDeviceToDevice);
    }
}

// round 3
// speedup vs baseline: 1.1463x; 1.1463x over previous
#include <cuda_runtime.h>
#include <cstdint>
#include <cstddef>

// Problem constants
#define BATCH   2
#define NPTS    8192
#define DIM     128
#define KOUT    17            // ranks 1..17 (skip self)
#define QT      64            // queries per CTA
#define CT      128           // candidates per tile
#define NTILES  (NPTS / CT)   // 64
#define QLD     68            // Q tile row pitch (floats)
#define CLD     132           // C tile row pitch (floats)

// smem layout (floats)
#define OFF_QS   0                        // Q tile: 128 x 68
#define OFF_CS   (DIM * QLD)              // 8704: C tile 128 x 132 (aliased: D tile 64x132, merge bufs)
#define OFF_SQQ  (OFF_CS + DIM * CLD)     // 25600
#define OFF_SQC  (OFF_SQQ + QT)           // 25664
#define SMEM_FLOATS (OFF_SQC + CT)        // 25792
#define SMEM_BYTES  (SMEM_FLOATS * 4)     // 103168

// Scratch (device globals: allocation-free rule)
__device__ float g_xT[BATCH * DIM * NPTS];   // x transposed: [b][k][n]
__device__ float g_sq[BATCH * NPTS];         // squared norms

// ---------------------------------------------------------------------------
// Prep kernel 1: tiled transpose x[b][n][k] -> g_xT[b][k][n]
// ---------------------------------------------------------------------------
__global__ void knn_transpose_kernel(const float* __restrict__ x) {
    __shared__ float t[32][33];
    const int b  = blockIdx.z;
    const int n0 = blockIdx.y * 32;
    const int k0 = blockIdx.x * 32;
    const int tx = threadIdx.x;
    const int ty = threadIdx.y;
#pragma unroll
    for (int i = 0; i < 32; i += 8)
        t[ty + i][tx] = x[((size_t)(b * NPTS + n0 + ty + i)) * DIM + k0 + tx];
    __syncthreads();
#pragma unroll
    for (int i = 0; i < 32; i += 8)
        g_xT[(size_t)b * DIM * NPTS + (size_t)(k0 + ty + i) * NPTS + n0 + tx] = t[tx][ty + i];
}

// ---------------------------------------------------------------------------
// Prep kernel 2: squared norms (one warp per point)
// ---------------------------------------------------------------------------
__global__ void knn_sq_kernel(const float* __restrict__ x) {
    const int n    = blockIdx.x * 8 + (threadIdx.x >> 5);
    const int lane = threadIdx.x & 31;
    float4 v = *(const float4*)(x + (size_t)n * DIM + lane * 4);
    float s = v.x * v.x + v.y * v.y + v.z * v.z + v.w * v.w;
#pragma unroll
    for (int o = 16; o > 0; o >>= 1) s += __shfl_xor_sync(0xFFFFFFFFu, s, o);
    if (lane == 0) g_sq[n] = s;
}

// ---------------------------------------------------------------------------
// Main fused GEMM + top-K kernel (2 CTAs/SM)
// ---------------------------------------------------------------------------
#define TRY_INSERT(dv, iv)                                                      \
    do {                                                                        \
        float _d = (dv);                                                        \
        if (_d <= th) {                                                         \
            int _i = (iv);                                                      \
            if (_d < bd[16] || (_d == bd[16] && _i < bi[16])) {                 \
                bd[16] = _d; bi[16] = _i;                                       \
                _Pragma("unroll")                                               \
                for (int _s = 16; _s > 0; --_s) {                               \
                    bool _sw = (bd[_s] < bd[_s - 1]) ||                         \
                               (bd[_s] == bd[_s - 1] && bi[_s] < bi[_s - 1]);   \
                    if (_sw) {                                                  \
                        float _td = bd[_s]; bd[_s] = bd[_s - 1]; bd[_s - 1] = _td; \
                        int _ti = bi[_s]; bi[_s] = bi[_s - 1]; bi[_s - 1] = _ti;  \
                    }                                                           \
                }                                                               \
                th = bd[16];                                                    \
            }                                                                   \
        }                                                                       \
    } while (0)

__global__ void __launch_bounds__(256, 2)
knn_main_kernel(float* __restrict__ outDist, float* __restrict__ outIdx) {
    extern __shared__ float sm[];
    float* Qs  = sm + OFF_QS;
    float* Cs  = sm + OFF_CS;     // C tile; aliased as D2 tile + merge bufs
    float* Ds  = Cs;              // D tile 64 x 132 (C dead after GEMM)
    float* sqQ = sm + OFF_SQQ;
    float* sqC = sm + OFF_SQC;

    const int tid = threadIdx.x;
    const int b   = blockIdx.y;
    const int q0  = blockIdx.x * QT;
    const float* xT  = g_xT + (size_t)b * DIM * NPTS;
    const float* sqg = g_sq + (size_t)b * NPTS;

    const float FINF = __int_as_float(0x7f800000);

    // ---- load Q tile (dim-major) ----
#pragma unroll
    for (int i = 0; i < 8; ++i) {
        int f = tid + i * 256;
        int k = f >> 4, c4 = f & 15;
        *(float4*)(Qs + k * QLD + c4 * 4) =
            *(const float4*)(xT + (size_t)k * NPTS + q0 + c4 * 4);
    }
    if (tid < QT) sqQ[tid] = sqg[q0 + tid];

    // ---- top-K state (registers) ----
    float bd[KOUT]; int bi[KOUT];
#pragma unroll
    for (int s = 0; s < KOUT; ++s) { bd[s] = FINF; bi[s] = 0x7FFFFFFF; }
    float th = FINF;

    const int rowt = tid >> 4;       // 0..15 -> query rows rowt*4 .. +3
    const int colt = tid & 15;       // 0..15 -> candidate cols colt*8 .. +7
    const int selR = tid >> 2;       // 0..63
    const int selC = (tid & 3) * 32; // 4 threads per query row

    for (int ct = 0; ct < NTILES; ++ct) {
        const int c0 = ct * CT;
        __syncthreads();   // prev selection (reads Ds=Cs) done before reload

        // ---- load C tile, split-block layout:
        //      row = [lo-float4 of group 0..15 | hi-float4 of group 0..15]
        //      col-group g (8 floats) -> lo at pos g, hi at pos 16+g ----
#pragma unroll
        for (int i = 0; i < 16; ++i) {
            int f = tid + i * 256;
            int k = f >> 5, c4 = f & 31;              // c4: float4 id 0..31
            int pos = (c4 & 1) * 16 + (c4 >> 1);      // even->lo block, odd->hi
            *(float4*)(Cs + k * CLD + pos * 4) =
                *(const float4*)(xT + (size_t)k * NPTS + c0 + c4 * 4);
        }
        if (tid < CT) sqC[tid] = sqg[c0 + tid];
        __syncthreads();

        // ---- 64x128x128 fp32 GEMM, 4x8 per thread; conflict-free B loads ----
        float acc[4][8];
#pragma unroll
        for (int i = 0; i < 4; ++i)
#pragma unroll
            for (int j = 0; j < 8; ++j) acc[i][j] = 0.f;

#pragma unroll 8
        for (int kk = 0; kk < DIM; ++kk) {
            float4 a  = *(const float4*)(Qs + kk * QLD + rowt * 4);
            float4 b0 = *(const float4*)(Cs + kk * CLD + colt * 4);        // lo
            float4 b1 = *(const float4*)(Cs + kk * CLD + 64 + colt * 4);   // hi
            float A[4] = {a.x, a.y, a.z, a.w};
            float B[8] = {b0.x, b0.y, b0.z, b0.w, b1.x, b1.y, b1.z, b1.w};
#pragma unroll
            for (int i = 0; i < 4; ++i)
#pragma unroll
                for (int j = 0; j < 8; ++j)
                    acc[i][j] = fmaf(A[i], B[j], acc[i][j]);
        }
        __syncthreads();   // all GEMM reads of Cs complete before Ds writes

        // ---- epilogue: d2 = max(sqi + sqj - 2*dot, 0); self -> +inf ----
        float si[4], sj[8];
#pragma unroll
        for (int i = 0; i < 4; ++i) si[i] = sqQ[rowt * 4 + i];
#pragma unroll
        for (int j = 0; j < 8; ++j) sj[j] = sqC[colt * 8 + j];
        const bool diagBlk = (c0 <= q0) && (q0 < c0 + CT);
#pragma unroll
        for (int i = 0; i < 4; ++i) {
            const int qg = q0 + rowt * 4 + i;
            float* drow = Ds + (rowt * 4 + i) * CLD + colt * 8;
#pragma unroll
            for (int g = 0; g < 8; g += 4) {
                float d0 = fmaxf(fmaf(-2.f, acc[i][g + 0], si[i] + sj[g + 0]), 0.f);
                float d1 = fmaxf(fmaf(-2.f, acc[i][g + 1], si[i] + sj[g + 1]), 0.f);
                float d2 = fmaxf(fmaf(-2.f, acc[i][g + 2], si[i] + sj[g + 2]), 0.f);
                float d3 = fmaxf(fmaf(-2.f, acc[i][g + 3], si[i] + sj[g + 3]), 0.f);
                if (diagBlk) {
                    const int cg = c0 + colt * 8 + g;
                    if (qg == cg + 0) d0 = FINF;
                    if (qg == cg + 1) d1 = FINF;
                    if (qg == cg + 2) d2 = FINF;
                    if (qg == cg + 3) d3 = FINF;
                }
                *(float4*)(drow + g) = make_float4(d0, d1, d2, d3);
            }
        }
        __syncthreads();

        // ---- selection: each thread scans 32 d2 values of one query row ----
        const float* drow = Ds + selR * CLD + selC;
#pragma unroll 1
        for (int j4 = 0; j4 < 8; ++j4) {
            float4 v = *(const float4*)(drow + j4 * 4);
            const int cb = c0 + selC + j4 * 4;
            TRY_INSERT(v.x, cb + 0);
            TRY_INSERT(v.y, cb + 1);
            TRY_INSERT(v.z, cb + 2);
            TRY_INSERT(v.w, cb + 3);
        }
    }

    // ---- merge 4 sub-lists per query, sqrt, stable resort, store ----
    __syncthreads();                       // selections done; reuse Cs region
    float* md = Cs;                        // 256*17 floats
    int*   mi = (int*)(Cs + 256 * KOUT);   // 256*17 ints (8704 floats total <= 16896)
#pragma unroll
    for (int s = 0; s < KOUT; ++s) { md[tid * KOUT + s] = bd[s]; mi[tid * KOUT + s] = bi[s]; }
    __syncthreads();

    if (tid < QT) {
        const float* dl[4]; const int* il[4]; int p[4];
#pragma unroll
        for (int l = 0; l < 4; ++l) {
            dl[l] = md + (tid * 4 + l) * KOUT;
            il[l] = mi + (tid * 4 + l) * KOUT;
            p[l] = 0;
        }
        float od[KOUT]; int oi[KOUT];
        for (int s = 0; s < KOUT; ++s) {   // sum(p)=s<=16 before each pick: no OOB
            float bdv = dl[0][p[0]]; int biv = il[0][p[0]]; int bl = 0;
#pragma unroll
            for (int l = 1; l < 4; ++l) {
                float dv = dl[l][p[l]]; int iv = il[l][p[l]];
                if (dv < bdv || (dv == bdv && iv < biv)) { bdv = dv; biv = iv; bl = l; }
            }
            od[s] = bdv; oi[s] = biv; ++p[bl];
        }
        for (int s = 0; s < KOUT; ++s) od[s] = sqrtf(od[s]);
        for (int s = 1; s < KOUT; ++s) {
            float dv = od[s]; int iv = oi[s]; int t = s - 1;
            while (t >= 0 && (od[t] > dv || (od[t] == dv && oi[t] > iv))) {
                od[t + 1] = od[t]; oi[t + 1] = oi[t]; --t;
            }
            od[t + 1] = dv; oi[t + 1] = iv;
        }
        const size_t base = (size_t)(b * NPTS + q0 + tid) * KOUT;
        for (int s = 0; s < KOUT; ++s) {
            outDist[base + s] = od[s];
            if (outIdx) outIdx[base + s] = (float)oi[s];
        }
    }
}

// ---------------------------------------------------------------------------
// Launch
// ---------------------------------------------------------------------------
extern "C" void kernel_launch(void* const* d_in, const int* in_sizes, int n_in,
                              void* d_out, int out_size) {
    const float* x = (const float*)d_in[0];
    float* out = (float*)d_out;

    const int ND = BATCH * NPTS * KOUT;       // 278528
    const int XE = BATCH * NPTS * DIM;        // 2097152

    float* outDist = out;
    float* outIdx  = (out_size >= 2 * ND) ? (out + ND) : nullptr;

    cudaFuncSetAttribute(knn_main_kernel,
                         cudaFuncAttributeMaxDynamicSharedMemorySize, SMEM_BYTES);

    knn_transpose_kernel<<<dim3(DIM / 32, NPTS / 32, BATCH), dim3(32, 8)>>>(x);
    knn_sq_kernel<<<(BATCH * NPTS) / 8, 256>>>(x);
    knn_main_kernel<<<dim3(NPTS / QT, BATCH), 256, SMEM_BYTES>>>(outDist, outIdx);

    if (out_size >= 2 * ND + 2 * XE) {
        cudaMemcpyAsync(out + 2 * ND, x, (size_t)XE * sizeof(float),
                        cudaMemcpyDeviceToDevice);
        cudaMemcpyAsync(out + 2 * ND + XE, x, (size_t)XE * sizeof(float),
                        cudaMemcpyDeviceToDevice);
    }
}